// round 12
// baseline (speedup 1.0000x reference)
#include <cuda_runtime.h>
#include <cuda_fp16.h>
#include <cstdint>

// LSTMPredictor: persistent-CTA fused 2-layer LSTM, WARP-SPECIALIZED.
// R12: warps 0-7 run layer 1 (recurrence), warps 8-15 run layer 2 (stateless
// emit path) concurrently on the same operand buffer; c-state published via
// double-buffered SMEM. One barrier per main step. B-fragments (one layer per
// warp, 32 regs) + c in registers; f16x2 packed activations (0.5 prescale in
// weights).
//
// Grid 128 CTAs x 512 thr, BT=64 rows/CTA, 1 CTA/SM (single wave).
// fp16 mma.m16n8k16: G[64 x 256pad] = A[64 x 64] @ W.
//   K: 0..50 h, 51 x/out, 52 bias(1.0), 53..63 zero
//   N: gate rows permuted n = 4j+q, q={i,f,g,o}; i/f/o rows pre-scaled 0.5.

#define NLAY_OFF 8192
#define WF_TOTAL 16384
#define ASTR 72
#define RSTR 9
#define BT   64
#define TPB  512
#define TSEQ 2048
#define TTOT 2112
#define NCTA 128

#define ABYTES (BT * ASTR * 2)          // 9216 B per A buffer
#define CB_N   4096                     // floats per c buffer

__device__ __align__(16) uint32_t d_Wf[WF_TOTAL];

__device__ __forceinline__ float tanh_ap(float x) {
    float y; asm("tanh.approx.f32 %0, %1;" : "=f"(y) : "f"(x)); return y;
}
__device__ __forceinline__ __half2 tanh2_ap(__half2 a) {
    uint32_t r, u = *(uint32_t*)&a;
    asm("tanh.approx.f16x2 %0, %1;" : "=r"(r) : "r"(u));
    return *(__half2*)&r;
}

#define LDSM4(d, addr)                                                        \
    asm volatile("ldmatrix.sync.aligned.m8n8.x4.shared.b16 {%0,%1,%2,%3}, [%4];" \
                 : "=r"(d[0]), "=r"(d[1]), "=r"(d[2]), "=r"(d[3]) : "r"(addr))

#define MMA_CHAIN(d0, d1, d2, d3, a, bset)                                    \
    _Pragma("unroll")                                                         \
    for (int kt = 0; kt < 4; kt++) {                                          \
        asm volatile(                                                         \
            "mma.sync.aligned.m16n8k16.row.col.f32.f16.f16.f32 "              \
            "{%0,%1,%2,%3},{%4,%5,%6,%7},{%8,%9},{%0,%1,%2,%3};\n"            \
            : "+f"(d0), "+f"(d1), "+f"(d2), "+f"(d3)                          \
            : "r"(a[kt][0]), "r"(a[kt][1]), "r"(a[kt][2]), "r"(a[kt][3]),     \
              "r"(bset[kt][0]), "r"(bset[kt][1]));                            \
    }

// ---------------------------------------------------------------------------
// Fragment-ordered fp16 weights (R4-R11 verified encoding; nt padded to 32).
// u = L*8192 + ((kt*32 + nt)*32 + lane)*2 + r
// pair = W[k0][n], W[k0+1][n]; k0 = kt*16 + r*8 + 2*(lane&3); n = nt*8 + (lane>>2)
// n -> gate row: j = n>>2, q = n&3, row = q*51 + j.  sigmoid rows (q != 2)
// pre-scaled by 0.5 (sig(x) = 0.5 + 0.5*tanh(0.5x)).
__global__ void prep_weights(const float* __restrict__ Wih1, const float* __restrict__ Whh1,
                             const float* __restrict__ bih1, const float* __restrict__ bhh1,
                             const float* __restrict__ Wih2, const float* __restrict__ Whh2,
                             const float* __restrict__ bih2, const float* __restrict__ bhh2) {
    int u = blockIdx.x * blockDim.x + threadIdx.x;
    if (u >= WF_TOTAL) return;
    int L    = u / NLAY_OFF;
    int w    = u - L * NLAY_OFF;
    int r    = w & 1;
    int lane = (w >> 1) & 31;
    int t2   = w >> 6;
    int nt   = t2 & 31;
    int kt   = t2 >> 5;
    int n    = nt * 8 + (lane >> 2);
    int k0   = kt * 16 + r * 8 + 2 * (lane & 3);
    float v[2];
#pragma unroll
    for (int i = 0; i < 2; i++) {
        int k = k0 + i;
        float val = 0.0f;
        if (n < 204) {
            int j = n >> 2, q = n & 3;
            int row = q * 51 + j;
            if (k < 51)
                val = (L == 0) ? Whh1[row * 51 + k]
                               : (Wih2[row * 51 + k] + Whh2[row * 51 + k]);
            else if (k == 51)
                val = (L == 0) ? Wih1[row] : 0.0f;
            else if (k == 52)
                val = (L == 0) ? (bih1[row] + bhh1[row]) : (bih2[row] + bhh2[row]);
            if (q != 2) val *= 0.5f;          // sigmoid pre-scale
        }
        v[i] = val;
    }
    __half2 h = __floats2half2_rn(v[0], v[1]);
    d_Wf[u] = *(uint32_t*)&h;
}

// ---------------------------------------------------------------------------
__device__ __forceinline__ void act_gates(float d0, float d1, float d2, float d3,
                                          int oddl,
                                          float& i_, float& f_, float& z_, float& o_) {
    const __half2 H05 = __float2half2_rn(0.5f);
    float s0 = oddl ? d0 : d2;
    float s1 = oddl ? d1 : d3;
    float x0 = __shfl_xor_sync(0xffffffffu, s0, 1);
    float x1 = __shfl_xor_sync(0xffffffffu, s1, 1);
    float gi = oddl ? x0 : d0;
    float gf = oddl ? x1 : d1;
    float gz = oddl ? d2 : x0;
    float go = oddl ? d3 : x1;
    __half2 t1  = tanh2_ap(__floats2half2_rn(gi, gf));
    __half2 sif = __hfma2(t1, H05, H05);
    __half2 t2  = tanh2_ap(__floats2half2_rn(gz, go));
    i_ = __low2float(sif);
    f_ = __high2float(sif);
    z_ = __low2float(t2);
    o_ = fmaf(__high2float(t2), 0.5f, 0.5f);
}

// ---------------------------------------------------------------------------
__global__ void __launch_bounds__(TPB, 1)
lstm_main(const float* __restrict__ x,
          const float* __restrict__ Wout, const float* __restrict__ bout,
          float* __restrict__ out) {
    extern __shared__ char sm[];
    __half* Asb = (__half*)sm;                        // [2][BT*ASTR]  18432 B
    float*  Cb  = (float*)(sm + 2 * ABYTES);          // [2][4096]     32768 B
    float*  Rs2 = (float*)(sm + 2 * ABYTES + 2 * CB_N * 4);  // [2][BT*RSTR] 4608 B

    const int tid  = threadIdx.x;
    const int lane = tid & 31;
    const int wrp  = tid >> 5;
    const int gb0  = blockIdx.x * BT;
    const int g    = lane >> 2, tig = lane & 3;
    const int oddl = tig & 1;
    const int wc   = wrp & 7;                  // warp column (n-slice)
    const int isL2 = (wrp >> 3);               // 0: layer1 warps, 1: layer2 warps
    const int ntBeg = wc * 4;
    const bool alive = (wc < 7);               // wc 7 -> nt 28..31 all dead

    // ---- one-time init ----
    for (int i = tid; i < 2 * BT * ASTR; i += TPB) {
        int col = i % ASTR;
        Asb[i] = __float2half_rn(col == 52 ? 1.0f : 0.0f);
    }
    for (int i = tid; i < 2 * CB_N; i += TPB) Cb[i] = 0.0f;
    for (int i = tid; i < 2 * BT * RSTR; i += TPB) Rs2[i] = 0.0f;
    if (tid < BT)
        Asb[tid * ASTR + 51] = __float2half_rn(x[(size_t)(gb0 + tid) * TSEQ]);

    // dead warps (7, 15) own x staging: warp7 rows 0-31, warp15 rows 32-63
    const int xrow = (wrp == 7) ? lane : 32 + lane;
    float xnext = (!alive) ? x[(size_t)(gb0 + xrow) * TSEQ + 1] : 0.0f;

    // B fragments -> registers (this warp's layer only)
    uint32_t Br[4][4][2];                      // [ni][kt][r]
#pragma unroll
    for (int ni = 0; ni < 4; ni++)
#pragma unroll
        for (int kt = 0; kt < 4; kt++) {
            uint2 v = *(const uint2*)&d_Wf[isL2 * NLAY_OFF +
                        (((kt * 32) + (ntBeg + ni)) * 32 + lane) * 2];
            Br[ni][kt][0] = v.x; Br[ni][kt][1] = v.y;
        }

    const float bo = bout[0];
    float woj[4];
#pragma unroll
    for (int ni = 0; ni < 4; ni++) {
        int j = 2 * (ntBeg + ni) + (tig >> 1);
        woj[ni] = (j < 51) ? Wout[j] : 0.0f;
    }

    float creg[4][4];                          // L1 warps only (site c-state)
#pragma unroll
    for (int mt = 0; mt < 4; mt++)
#pragma unroll
        for (int ni = 0; ni < 4; ni++) creg[mt][ni] = 0.0f;

    // ldmatrix per-lane byte offset
    const int lm = lane >> 3;
    const uint32_t aOff = (uint32_t)((((lm & 1) * 8 + (lane & 7)) * ASTR +
                                      (lm >> 1) * 8) * 2);
    const uint32_t aBase = (uint32_t)__cvta_generic_to_shared(Asb);
    const int rowBase = g + (oddl ? 8 : 0);
    // per-lane site index base in Cb: ((wc*4+mt)*4+ni)*32 + lane
    const int cbBase = (wc * 16) * 32 + lane;

    __syncthreads();

    // ================= main phase: k = 0..TSEQ-1, ONE barrier/step ==========
    // L1 warps: h(k),c(k) from cur=[h(k-1),x(k),1].  L2 warps: out(k-1) from
    // cur + c(k-1).  Dead warps: stage x(k+1) into nxt.
#pragma unroll 1
    for (int k = 0; k < TSEQ; k++) {
        const uint32_t curB = aBase + (uint32_t)((k & 1) * ABYTES);
        __half* An = Asb + ((k & 1) ^ 1) * (BT * ASTR);
        float* CbW = Cb + (k & 1) * CB_N;          // L1 writes c(k)
        float* CbR = Cb + ((k & 1) ^ 1) * CB_N;    // L2 reads  c(k-1)

        if (alive) {
            if (!isL2) {
                // ---------- Layer 1 ----------
#pragma unroll
                for (int mt = 0; mt < 4; mt++) {
                    uint32_t a[4][4];
#pragma unroll
                    for (int kt = 0; kt < 4; kt++)
                        LDSM4(a[kt], curB + aOff + (uint32_t)((mt * 16 * ASTR + kt * 16) * 2));
                    const int myrow = mt * 16 + rowBase;
#pragma unroll
                    for (int ni = 0; ni < 4; ni++) {
                        if (ntBeg + ni <= 25) {
                            float d0 = 0.f, d1 = 0.f, d2 = 0.f, d3 = 0.f;
                            MMA_CHAIN(d0, d1, d2, d3, a, Br[ni]);
                            float i1, f1, z1, o1;
                            act_gates(d0, d1, d2, d3, oddl, i1, f1, z1, o1);
                            float c = fmaf(f1, creg[mt][ni], i1 * z1);
                            creg[mt][ni] = c;
                            CbW[cbBase + (mt * 4 + ni) * 32] = c;
                            int j = 2 * (ntBeg + ni) + (tig >> 1);
                            if (j < 51)
                                An[myrow * ASTR + j] = __float2half_rn(o1 * tanh_ap(c));
                        }
                    }
                }
            } else {
                // ---------- Layer 2 ----------
                float racc[4] = {0.f, 0.f, 0.f, 0.f};
#pragma unroll
                for (int mt = 0; mt < 4; mt++) {
                    uint32_t a[4][4];
#pragma unroll
                    for (int kt = 0; kt < 4; kt++)
                        LDSM4(a[kt], curB + aOff + (uint32_t)((mt * 16 * ASTR + kt * 16) * 2));
#pragma unroll
                    for (int ni = 0; ni < 4; ni++) {
                        if (ntBeg + ni <= 25) {
                            float e0 = 0.f, e1 = 0.f, e2 = 0.f, e3 = 0.f;
                            MMA_CHAIN(e0, e1, e2, e3, a, Br[ni]);
                            float i2, f2, z2, o2;
                            act_gates(e0, e1, e2, e3, oddl, i2, f2, z2, o2);
                            float cold = CbR[cbBase + (mt * 4 + ni) * 32];
                            float c2 = fmaf(f2, cold, i2 * z2);
                            racc[mt] += o2 * tanh_ap(c2) * woj[ni];
                        }
                    }
                }
#pragma unroll
                for (int mt = 0; mt < 4; mt++)
                    racc[mt] += __shfl_xor_sync(0xffffffffu, racc[mt], 2);
                if ((tig >> 1) == 0) {
                    float* R = Rs2 + (k & 1) * (BT * RSTR);
#pragma unroll
                    for (int mt = 0; mt < 4; mt++)
                        R[(mt * 16 + rowBase) * RSTR + wc] = racc[mt];
                }
            }
        } else {
            // dead warps 7/15: stage x(k+1), prefetch x(k+2)
            if (k + 1 < TSEQ)
                An[xrow * ASTR + 51] = __float2half_rn(xnext);
            if (k + 2 < TSEQ)
                xnext = x[(size_t)(gb0 + xrow) * TSEQ + (k + 2)];
        }
        __syncthreads();

        // emit out(k-1)
        if (k >= 1) {
            int row = tid >> 3, q = tid & 7;
            float s = Rs2[(k & 1) * (BT * RSTR) + row * RSTR + q];
            s += __shfl_xor_sync(0xffffffffu, s, 1);
            s += __shfl_xor_sync(0xffffffffu, s, 2);
            s += __shfl_xor_sync(0xffffffffu, s, 4);
            if (q == 0)
                out[(size_t)(gb0 + row) * TTOT + (k - 1)] = s + bo;
        }
    }

    // ================= autoregressive tail: t = TSEQ..TTOT-1 ================
#pragma unroll 1
    for (int t = TSEQ; t < TTOT; t++) {
        const uint32_t curB = aBase + (uint32_t)((t & 1) * ABYTES);
        __half* Ac = Asb + (t & 1) * (BT * ASTR);
        __half* An = Asb + ((t & 1) ^ 1) * (BT * ASTR);
        float* CbW = Cb + (t & 1) * CB_N;
        float* CbR = Cb + ((t & 1) ^ 1) * CB_N;

        // L2 warps: out(t-1) partials
        if (alive && isL2) {
            float racc[4] = {0.f, 0.f, 0.f, 0.f};
#pragma unroll
            for (int mt = 0; mt < 4; mt++) {
                uint32_t a[4][4];
#pragma unroll
                for (int kt = 0; kt < 4; kt++)
                    LDSM4(a[kt], curB + aOff + (uint32_t)((mt * 16 * ASTR + kt * 16) * 2));
#pragma unroll
                for (int ni = 0; ni < 4; ni++) {
                    if (ntBeg + ni <= 25) {
                        float e0 = 0.f, e1 = 0.f, e2 = 0.f, e3 = 0.f;
                        MMA_CHAIN(e0, e1, e2, e3, a, Br[ni]);
                        float i2, f2, z2, o2;
                        act_gates(e0, e1, e2, e3, oddl, i2, f2, z2, o2);
                        float cold = CbR[cbBase + (mt * 4 + ni) * 32];
                        float c2 = fmaf(f2, cold, i2 * z2);
                        racc[mt] += o2 * tanh_ap(c2) * woj[ni];
                    }
                }
            }
#pragma unroll
            for (int mt = 0; mt < 4; mt++)
                racc[mt] += __shfl_xor_sync(0xffffffffu, racc[mt], 2);
            if ((tig >> 1) == 0) {
#pragma unroll
                for (int mt = 0; mt < 4; mt++)
                    Rs2[(mt * 16 + rowBase) * RSTR + wc] = racc[mt];
            }
        }
        __syncthreads();

        // emit out(t-1), feed back into cur's x slot
        {
            int row = tid >> 3, q = tid & 7;
            float s = Rs2[row * RSTR + q];
            s += __shfl_xor_sync(0xffffffffu, s, 1);
            s += __shfl_xor_sync(0xffffffffu, s, 2);
            s += __shfl_xor_sync(0xffffffffu, s, 4);
            if (q == 0) {
                float o = s + bo;
                out[(size_t)(gb0 + row) * TTOT + (t - 1)] = o;
                Ac[row * ASTR + 51] = __float2half_rn(o);
            }
        }
        __syncthreads();

        // L1 warps: h(t), c(t)
        if (alive && !isL2) {
#pragma unroll
            for (int mt = 0; mt < 4; mt++) {
                uint32_t a[4][4];
#pragma unroll
                for (int kt = 0; kt < 4; kt++)
                    LDSM4(a[kt], curB + aOff + (uint32_t)((mt * 16 * ASTR + kt * 16) * 2));
                const int myrow = mt * 16 + rowBase;
#pragma unroll
                for (int ni = 0; ni < 4; ni++) {
                    if (ntBeg + ni <= 25) {
                        float d0 = 0.f, d1 = 0.f, d2 = 0.f, d3 = 0.f;
                        MMA_CHAIN(d0, d1, d2, d3, a, Br[ni]);
                        float i1, f1, z1, o1;
                        act_gates(d0, d1, d2, d3, oddl, i1, f1, z1, o1);
                        float c = fmaf(f1, creg[mt][ni], i1 * z1);
                        creg[mt][ni] = c;
                        CbW[cbBase + (mt * 4 + ni) * 32] = c;
                        int j = 2 * (ntBeg + ni) + (tig >> 1);
                        if (j < 51)
                            An[myrow * ASTR + j] = __float2half_rn(o1 * tanh_ap(c));
                    }
                }
            }
        }
        __syncthreads();
    }

    // ================= final emit: out(TTOT-1) ==============================
    {
        const uint32_t curB = aBase + (uint32_t)((TTOT & 1) * ABYTES);
        float* CbR = Cb + ((TTOT & 1) ^ 1) * CB_N;
        if (alive && isL2) {
            float racc[4] = {0.f, 0.f, 0.f, 0.f};
#pragma unroll
            for (int mt = 0; mt < 4; mt++) {
                uint32_t a[4][4];
#pragma unroll
                for (int kt = 0; kt < 4; kt++)
                    LDSM4(a[kt], curB + aOff + (uint32_t)((mt * 16 * ASTR + kt * 16) * 2));
#pragma unroll
                for (int ni = 0; ni < 4; ni++) {
                    if (ntBeg + ni <= 25) {
                        float e0 = 0.f, e1 = 0.f, e2 = 0.f, e3 = 0.f;
                        MMA_CHAIN(e0, e1, e2, e3, a, Br[ni]);
                        float i2, f2, z2, o2;
                        act_gates(e0, e1, e2, e3, oddl, i2, f2, z2, o2);
                        float cold = CbR[cbBase + (mt * 4 + ni) * 32];
                        float c2 = fmaf(f2, cold, i2 * z2);
                        racc[mt] += o2 * tanh_ap(c2) * woj[ni];
                    }
                }
            }
#pragma unroll
            for (int mt = 0; mt < 4; mt++)
                racc[mt] += __shfl_xor_sync(0xffffffffu, racc[mt], 2);
            if ((tig >> 1) == 0) {
#pragma unroll
                for (int mt = 0; mt < 4; mt++)
                    Rs2[(mt * 16 + rowBase) * RSTR + wc] = racc[mt];
            }
        }
        __syncthreads();
        {
            int row = tid >> 3, q = tid & 7;
            float s = Rs2[row * RSTR + q];
            s += __shfl_xor_sync(0xffffffffu, s, 1);
            s += __shfl_xor_sync(0xffffffffu, s, 2);
            s += __shfl_xor_sync(0xffffffffu, s, 4);
            if (q == 0)
                out[(size_t)(gb0 + row) * TTOT + (TTOT - 1)] = s + bo;
        }
    }
}

// ---------------------------------------------------------------------------
extern "C" void kernel_launch(void* const* d_in, const int* in_sizes, int n_in,
                              void* d_out, int out_size) {
    const float* x    = (const float*)d_in[0];
    const float* Wih1 = (const float*)d_in[1];
    const float* Whh1 = (const float*)d_in[2];
    const float* bih1 = (const float*)d_in[3];
    const float* bhh1 = (const float*)d_in[4];
    const float* Wih2 = (const float*)d_in[5];
    const float* Whh2 = (const float*)d_in[6];
    const float* bih2 = (const float*)d_in[7];
    const float* bhh2 = (const float*)d_in[8];
    const float* Wout = (const float*)d_in[9];
    const float* bouT = (const float*)d_in[10];
    float* out = (float*)d_out;

    const int smem = 2 * ABYTES + 2 * CB_N * 4 + 2 * BT * RSTR * 4;  // 55808
    cudaFuncSetAttribute(lstm_main, cudaFuncAttributeMaxDynamicSharedMemorySize, smem);

    prep_weights<<<64, 256>>>(Wih1, Whh1, bih1, bhh1, Wih2, Whh2, bih2, bhh2);
    lstm_main<<<NCTA, TPB, smem>>>(x, Wout, bouT, out);
}

// round 14
// speedup vs baseline: 1.9125x; 1.9125x over previous
#include <cuda_runtime.h>
#include <cuda_fp16.h>
#include <cstdint>

// LSTMPredictor: persistent-CTA fused 2-layer LSTM, layer-pipelined (R8 base).
// R13: gate-PAIR weight permutation -> activation needs NO shuffles.
//   N space: 32 tiles of 8. Tile nt: pair p = nt>>1, half hh = nt&1.
//   Col-in-tile cl: jl = cl>>1, gpar = cl&1. j = p*4 + jl, gate q' = hh*2+gpar
//   (0=i,1=f,2=g,3=o). So in the m16n8 D fragment, lane (g,tig) of the EVEN
//   tile holds (i,f) of j=4p+tig for rows g,g+8, and the ODD tile holds (g,o)
//   of the same j -> all 4 gates per site land in one lane natively.
// L2(k-1) and L1(k) share A-fragments; one barrier per main step; x staged by
// dead warp 7. Weights (64 regs) + c-state in registers; f16x2 packed
// activations (0.5 prescale baked into sigmoid-gate weights).
//
// Grid 256 CTAs x 256 thr, BT=32 rows/CTA, 2 CTAs/SM (independent slip).

#define NLAY_OFF 8192
#define WF_TOTAL 16384
#define ASTR 72
#define RSTR 9
#define BT   32
#define TPB  256
#define TSEQ 2048
#define TTOT 2112
#define NCTA 256

__device__ __align__(16) uint32_t d_Wf[WF_TOTAL];

__device__ __forceinline__ float tanh_ap(float x) {
    float y; asm("tanh.approx.f32 %0, %1;" : "=f"(y) : "f"(x)); return y;
}
__device__ __forceinline__ __half2 tanh2_ap(__half2 a) {
    uint32_t r, u = *(uint32_t*)&a;
    asm("tanh.approx.f16x2 %0, %1;" : "=r"(r) : "r"(u));
    return *(__half2*)&r;
}

#define LDSM4(d, addr)                                                        \
    asm volatile("ldmatrix.sync.aligned.m8n8.x4.shared.b16 {%0,%1,%2,%3}, [%4];" \
                 : "=r"(d[0]), "=r"(d[1]), "=r"(d[2]), "=r"(d[3]) : "r"(addr))

#define MMA_CHAIN(d0, d1, d2, d3, a, bset)                                    \
    _Pragma("unroll")                                                         \
    for (int kt = 0; kt < 4; kt++) {                                          \
        asm volatile(                                                         \
            "mma.sync.aligned.m16n8k16.row.col.f32.f16.f16.f32 "              \
            "{%0,%1,%2,%3},{%4,%5,%6,%7},{%8,%9},{%0,%1,%2,%3};\n"            \
            : "+f"(d0), "+f"(d1), "+f"(d2), "+f"(d3)                          \
            : "r"(a[kt][0]), "r"(a[kt][1]), "r"(a[kt][2]), "r"(a[kt][3]),     \
              "r"(bset[kt][0]), "r"(bset[kt][1]));                            \
    }

// ---------------------------------------------------------------------------
// Fragment-ordered fp16 weights, gate-PAIR permutation.
// u = L*8192 + ((kt*32 + nt)*32 + lane)*2 + r
// pair = W[k0][n], W[k0+1][n]; k0 = kt*16 + r*8 + 2*(lane&3); col cl = lane>>2.
// n -> gate row: p = nt>>1, hh = nt&1, jl = cl>>1, gpar = cl&1;
//   j = p*4 + jl, q' = hh*2 + gpar, row = q'*51 + j (valid j < 51).
// K rows: k<51 h-weights, k==51 x-weight (L1 only), k==52 bias. Sigmoid gates
// (q' != 2) pre-scaled by 0.5.
__global__ void prep_weights(const float* __restrict__ Wih1, const float* __restrict__ Whh1,
                             const float* __restrict__ bih1, const float* __restrict__ bhh1,
                             const float* __restrict__ Wih2, const float* __restrict__ Whh2,
                             const float* __restrict__ bih2, const float* __restrict__ bhh2) {
    int u = blockIdx.x * blockDim.x + threadIdx.x;
    if (u >= WF_TOTAL) return;
    int L    = u / NLAY_OFF;
    int w    = u - L * NLAY_OFF;
    int r    = w & 1;
    int lane = (w >> 1) & 31;
    int t2   = w >> 6;
    int nt   = t2 & 31;
    int kt   = t2 >> 5;
    int cl   = lane >> 2;
    int p    = nt >> 1, hh = nt & 1;
    int jl   = cl >> 1, gpar = cl & 1;
    int j    = p * 4 + jl;
    int qp   = hh * 2 + gpar;
    int k0   = kt * 16 + r * 8 + 2 * (lane & 3);
    float v[2];
#pragma unroll
    for (int i = 0; i < 2; i++) {
        int k = k0 + i;
        float val = 0.0f;
        if (j < 51) {
            int row = qp * 51 + j;
            if (k < 51)
                val = (L == 0) ? Whh1[row * 51 + k]
                               : (Wih2[row * 51 + k] + Whh2[row * 51 + k]);
            else if (k == 51)
                val = (L == 0) ? Wih1[row] : 0.0f;
            else if (k == 52)
                val = (L == 0) ? (bih1[row] + bhh1[row]) : (bih2[row] + bhh2[row]);
            if (qp != 2) val *= 0.5f;          // sigmoid pre-scale
        }
        v[i] = val;
    }
    __half2 h = __floats2half2_rn(v[0], v[1]);
    d_Wf[u] = *(uint32_t*)&h;
}

// ---------------------------------------------------------------------------
// gate activation: gA0=0.5*g_i, gA1=0.5*g_f, gB0=g_z, gB1=0.5*g_o
__device__ __forceinline__ void site_act(float gA0, float gA1, float gB0, float gB1,
                                         float& i_, float& f_, float& z_, float& o_) {
    const __half2 H05 = __float2half2_rn(0.5f);
    __half2 t1  = tanh2_ap(__floats2half2_rn(gA0, gA1));
    __half2 sif = __hfma2(t1, H05, H05);
    __half2 t2  = tanh2_ap(__floats2half2_rn(gB0, gB1));
    i_ = __low2float(sif);
    f_ = __high2float(sif);
    z_ = __low2float(t2);
    o_ = fmaf(__high2float(t2), 0.5f, 0.5f);
}

// ---------------------------------------------------------------------------
__global__ void __launch_bounds__(TPB, 2)
lstm_main(const float* __restrict__ x,
          const float* __restrict__ Wout, const float* __restrict__ bout,
          float* __restrict__ out) {
    __shared__ __half Asb[2][BT * ASTR];
    __shared__ float  Rs2d[2][BT * RSTR];

    const int tid  = threadIdx.x;
    const int lane = tid & 31;
    const int wrp  = tid >> 5;
    const int gb0  = blockIdx.x * BT;
    const int g    = lane >> 2, tig = lane & 3;
    const int pBase = wrp * 2;                 // pairs pBase, pBase+1; valid <= 12
    const bool alive = (wrp < 7);              // warp 7: x staging only

    // ---- one-time init ----
    for (int i = tid; i < BT * ASTR; i += TPB) {
        __half v = __float2half_rn((i % ASTR) == 52 ? 1.0f : 0.0f);
        Asb[0][i] = v; Asb[1][i] = v;
    }
    for (int i = tid; i < BT * RSTR; i += TPB) {
        Rs2d[0][i] = 0.0f; Rs2d[1][i] = 0.0f;
    }
    if (tid < BT)
        Asb[0][tid * ASTR + 51] = __float2half_rn(x[(size_t)(gb0 + tid) * TSEQ]);
    float xnext = (wrp == 7) ? x[(size_t)(gb0 + lane) * TSEQ + 1] : 0.0f;

    // B fragments -> registers: [L][pi][tile][kt][r]
    uint32_t Br[2][2][2][4][2];
#pragma unroll
    for (int L = 0; L < 2; L++)
#pragma unroll
        for (int pi = 0; pi < 2; pi++)
#pragma unroll
            for (int tl = 0; tl < 2; tl++)
#pragma unroll
                for (int kt = 0; kt < 4; kt++) {
                    int nt = (pBase + pi) * 2 + tl;
                    uint2 v = *(const uint2*)&d_Wf[L * NLAY_OFF +
                                (((kt * 32) + nt) * 32 + lane) * 2];
                    Br[L][pi][tl][kt][0] = v.x; Br[L][pi][tl][kt][1] = v.y;
                }

    const float bo = bout[0];
    float woj[2];
#pragma unroll
    for (int pi = 0; pi < 2; pi++) {
        int j = (pBase + pi) * 4 + tig;
        woj[pi] = (j < 51) ? Wout[j] : 0.0f;
    }

    float creg[2][2][2];                       // [mt][pi][row: g / g+8]
#pragma unroll
    for (int mt = 0; mt < 2; mt++)
#pragma unroll
        for (int pi = 0; pi < 2; pi++) {
            creg[mt][pi][0] = 0.0f; creg[mt][pi][1] = 0.0f;
        }

    // ldmatrix per-lane byte offset
    const int lm = lane >> 3;
    const uint32_t aOff = (uint32_t)((((lm & 1) * 8 + (lane & 7)) * ASTR +
                                      (lm >> 1) * 8) * 2);
    const uint32_t aB0 = (uint32_t)__cvta_generic_to_shared(&Asb[0][0]);
    const uint32_t aB1 = (uint32_t)__cvta_generic_to_shared(&Asb[1][0]);

    __syncthreads();

    // ================= main pipelined phase: k = 0..TSEQ-1 ==================
    // iter k: A-frags of [h1(k-1), x(k), 1] feed BOTH L2(k-1) (old creg ->
    // out(k-1)) and L1(k) (updates creg, h1(k) -> nxt). ONE barrier/iter.
#pragma unroll 1
    for (int k = 0; k < TSEQ; k++) {
        const uint32_t curB = (k & 1) ? aB1 : aB0;
        __half* An = Asb[(k & 1) ^ 1];
        float*  Rw = Rs2d[k & 1];

        if (alive) {
            float racc[4] = {0.f, 0.f, 0.f, 0.f};   // [mt*2 + rowsel]
#pragma unroll
            for (int mt = 0; mt < 2; mt++) {
                uint32_t a[4][4];
#pragma unroll
                for (int kt = 0; kt < 4; kt++)
                    LDSM4(a[kt], curB + aOff + (uint32_t)((mt * 16 * ASTR + kt * 16) * 2));
#pragma unroll
                for (int pi = 0; pi < 2; pi++) {
                    if (pBase + pi <= 12) {
                        const int j = (pBase + pi) * 4 + tig;
                        // ---- L2(k-1): stateless, old creg ----
                        float eA0 = 0.f, eA1 = 0.f, eA2 = 0.f, eA3 = 0.f;
                        float eB0 = 0.f, eB1 = 0.f, eB2 = 0.f, eB3 = 0.f;
                        MMA_CHAIN(eA0, eA1, eA2, eA3, a, Br[1][pi][0]);
                        MMA_CHAIN(eB0, eB1, eB2, eB3, a, Br[1][pi][1]);
                        {
                            float i2, f2, z2, o2;
                            site_act(eA0, eA1, eB0, eB1, i2, f2, z2, o2);
                            float c2 = fmaf(f2, creg[mt][pi][0], i2 * z2);
                            racc[mt * 2 + 0] += o2 * tanh_ap(c2) * woj[pi];
                            site_act(eA2, eA3, eB2, eB3, i2, f2, z2, o2);
                            c2 = fmaf(f2, creg[mt][pi][1], i2 * z2);
                            racc[mt * 2 + 1] += o2 * tanh_ap(c2) * woj[pi];
                        }
                        // ---- L1(k): recurrent, updates creg ----
                        float dA0 = 0.f, dA1 = 0.f, dA2 = 0.f, dA3 = 0.f;
                        float dB0 = 0.f, dB1 = 0.f, dB2 = 0.f, dB3 = 0.f;
                        MMA_CHAIN(dA0, dA1, dA2, dA3, a, Br[0][pi][0]);
                        MMA_CHAIN(dB0, dB1, dB2, dB3, a, Br[0][pi][1]);
                        {
                            float i1, f1, z1, o1;
                            site_act(dA0, dA1, dB0, dB1, i1, f1, z1, o1);
                            float c = fmaf(f1, creg[mt][pi][0], i1 * z1);
                            creg[mt][pi][0] = c;
                            if (j < 51)
                                An[(mt * 16 + g) * ASTR + j] =
                                    __float2half_rn(o1 * tanh_ap(c));
                            site_act(dA2, dA3, dB2, dB3, i1, f1, z1, o1);
                            c = fmaf(f1, creg[mt][pi][1], i1 * z1);
                            creg[mt][pi][1] = c;
                            if (j < 51)
                                An[(mt * 16 + g + 8) * ASTR + j] =
                                    __float2half_rn(o1 * tanh_ap(c));
                        }
                    }
                }
            }
            // reduce racc over tig (lanes 4g..4g+3)
#pragma unroll
            for (int rr = 0; rr < 4; rr++) {
                racc[rr] += __shfl_xor_sync(0xffffffffu, racc[rr], 1);
                racc[rr] += __shfl_xor_sync(0xffffffffu, racc[rr], 2);
            }
            if (tig == 0) {
                Rw[g * RSTR + wrp]        = racc[0];
                Rw[(g + 8) * RSTR + wrp]  = racc[1];
                Rw[(g + 16) * RSTR + wrp] = racc[2];
                Rw[(g + 24) * RSTR + wrp] = racc[3];
            }
        } else {
            // warp 7: stage x(k+1) into nxt; prefetch x(k+2)
            if (k + 1 < TSEQ)
                An[lane * ASTR + 51] = __float2half_rn(xnext);
            if (k + 2 < TSEQ)
                xnext = x[(size_t)(gb0 + lane) * TSEQ + (k + 2)];
        }
        __syncthreads();                        // the ONE barrier

        // emit out(k-1)
        if (k >= 1) {
            int row = tid >> 3, q = tid & 7;
            float s = Rs2d[k & 1][row * RSTR + q];
            s += __shfl_xor_sync(0xffffffffu, s, 1);
            s += __shfl_xor_sync(0xffffffffu, s, 2);
            s += __shfl_xor_sync(0xffffffffu, s, 4);
            if (q == 0)
                out[(size_t)(gb0 + row) * TTOT + (k - 1)] = s + bo;
        }
    }

    // ================= autoregressive tail: t = TSEQ..TTOT-1 ================
#pragma unroll 1
    for (int t = TSEQ; t < TTOT; t++) {
        const uint32_t curB = (t & 1) ? aB1 : aB0;
        __half* Ac = Asb[t & 1];
        __half* An = Asb[(t & 1) ^ 1];

        // ---- L2 on h1(t-1), c(t-1) -> out(t-1) ----
        if (alive) {
            float racc[4] = {0.f, 0.f, 0.f, 0.f};
#pragma unroll
            for (int mt = 0; mt < 2; mt++) {
                uint32_t a[4][4];
#pragma unroll
                for (int kt = 0; kt < 4; kt++)
                    LDSM4(a[kt], curB + aOff + (uint32_t)((mt * 16 * ASTR + kt * 16) * 2));
#pragma unroll
                for (int pi = 0; pi < 2; pi++) {
                    if (pBase + pi <= 12) {
                        float eA0 = 0.f, eA1 = 0.f, eA2 = 0.f, eA3 = 0.f;
                        float eB0 = 0.f, eB1 = 0.f, eB2 = 0.f, eB3 = 0.f;
                        MMA_CHAIN(eA0, eA1, eA2, eA3, a, Br[1][pi][0]);
                        MMA_CHAIN(eB0, eB1, eB2, eB3, a, Br[1][pi][1]);
                        float i2, f2, z2, o2;
                        site_act(eA0, eA1, eB0, eB1, i2, f2, z2, o2);
                        float c2 = fmaf(f2, creg[mt][pi][0], i2 * z2);
                        racc[mt * 2 + 0] += o2 * tanh_ap(c2) * woj[pi];
                        site_act(eA2, eA3, eB2, eB3, i2, f2, z2, o2);
                        c2 = fmaf(f2, creg[mt][pi][1], i2 * z2);
                        racc[mt * 2 + 1] += o2 * tanh_ap(c2) * woj[pi];
                    }
                }
            }
#pragma unroll
            for (int rr = 0; rr < 4; rr++) {
                racc[rr] += __shfl_xor_sync(0xffffffffu, racc[rr], 1);
                racc[rr] += __shfl_xor_sync(0xffffffffu, racc[rr], 2);
            }
            if (tig == 0) {
                Rs2d[0][g * RSTR + wrp]        = racc[0];
                Rs2d[0][(g + 8) * RSTR + wrp]  = racc[1];
                Rs2d[0][(g + 16) * RSTR + wrp] = racc[2];
                Rs2d[0][(g + 24) * RSTR + wrp] = racc[3];
            }
        }
        __syncthreads();

        // emit out(t-1), feed back into cur's x slot
        {
            int row = tid >> 3, q = tid & 7;
            float s = Rs2d[0][row * RSTR + q];
            s += __shfl_xor_sync(0xffffffffu, s, 1);
            s += __shfl_xor_sync(0xffffffffu, s, 2);
            s += __shfl_xor_sync(0xffffffffu, s, 4);
            if (q == 0) {
                float o = s + bo;
                out[(size_t)(gb0 + row) * TTOT + (t - 1)] = o;
                Ac[row * ASTR + 51] = __float2half_rn(o);
            }
        }
        __syncthreads();

        // ---- L1 on [h1(t-1), out(t-1)] -> h1(t), c(t) ----
        if (alive) {
#pragma unroll
            for (int mt = 0; mt < 2; mt++) {
                uint32_t a[4][4];
#pragma unroll
                for (int kt = 0; kt < 4; kt++)
                    LDSM4(a[kt], curB + aOff + (uint32_t)((mt * 16 * ASTR + kt * 16) * 2));
#pragma unroll
                for (int pi = 0; pi < 2; pi++) {
                    if (pBase + pi <= 12) {
                        const int j = (pBase + pi) * 4 + tig;
                        float dA0 = 0.f, dA1 = 0.f, dA2 = 0.f, dA3 = 0.f;
                        float dB0 = 0.f, dB1 = 0.f, dB2 = 0.f, dB3 = 0.f;
                        MMA_CHAIN(dA0, dA1, dA2, dA3, a, Br[0][pi][0]);
                        MMA_CHAIN(dB0, dB1, dB2, dB3, a, Br[0][pi][1]);
                        float i1, f1, z1, o1;
                        site_act(dA0, dA1, dB0, dB1, i1, f1, z1, o1);
                        float c = fmaf(f1, creg[mt][pi][0], i1 * z1);
                        creg[mt][pi][0] = c;
                        if (j < 51)
                            An[(mt * 16 + g) * ASTR + j] =
                                __float2half_rn(o1 * tanh_ap(c));
                        site_act(dA2, dA3, dB2, dB3, i1, f1, z1, o1);
                        c = fmaf(f1, creg[mt][pi][1], i1 * z1);
                        creg[mt][pi][1] = c;
                        if (j < 51)
                            An[(mt * 16 + g + 8) * ASTR + j] =
                                __float2half_rn(o1 * tanh_ap(c));
                    }
                }
            }
        }
        __syncthreads();
    }

    // ================= final emit: out(TTOT-1) ==============================
    {
        const uint32_t curB = (TTOT & 1) ? aB1 : aB0;
        if (alive) {
            float racc[4] = {0.f, 0.f, 0.f, 0.f};
#pragma unroll
            for (int mt = 0; mt < 2; mt++) {
                uint32_t a[4][4];
#pragma unroll
                for (int kt = 0; kt < 4; kt++)
                    LDSM4(a[kt], curB + aOff + (uint32_t)((mt * 16 * ASTR + kt * 16) * 2));
#pragma unroll
                for (int pi = 0; pi < 2; pi++) {
                    if (pBase + pi <= 12) {
                        float eA0 = 0.f, eA1 = 0.f, eA2 = 0.f, eA3 = 0.f;
                        float eB0 = 0.f, eB1 = 0.f, eB2 = 0.f, eB3 = 0.f;
                        MMA_CHAIN(eA0, eA1, eA2, eA3, a, Br[1][pi][0]);
                        MMA_CHAIN(eB0, eB1, eB2, eB3, a, Br[1][pi][1]);
                        float i2, f2, z2, o2;
                        site_act(eA0, eA1, eB0, eB1, i2, f2, z2, o2);
                        float c2 = fmaf(f2, creg[mt][pi][0], i2 * z2);
                        racc[mt * 2 + 0] += o2 * tanh_ap(c2) * woj[pi];
                        site_act(eA2, eA3, eB2, eB3, i2, f2, z2, o2);
                        c2 = fmaf(f2, creg[mt][pi][1], i2 * z2);
                        racc[mt * 2 + 1] += o2 * tanh_ap(c2) * woj[pi];
                    }
                }
            }
#pragma unroll
            for (int rr = 0; rr < 4; rr++) {
                racc[rr] += __shfl_xor_sync(0xffffffffu, racc[rr], 1);
                racc[rr] += __shfl_xor_sync(0xffffffffu, racc[rr], 2);
            }
            if (tig == 0) {
                Rs2d[0][g * RSTR + wrp]        = racc[0];
                Rs2d[0][(g + 8) * RSTR + wrp]  = racc[1];
                Rs2d[0][(g + 16) * RSTR + wrp] = racc[2];
                Rs2d[0][(g + 24) * RSTR + wrp] = racc[3];
            }
        }
        __syncthreads();
        {
            int row = tid >> 3, q = tid & 7;
            float s = Rs2d[0][row * RSTR + q];
            s += __shfl_xor_sync(0xffffffffu, s, 1);
            s += __shfl_xor_sync(0xffffffffu, s, 2);
            s += __shfl_xor_sync(0xffffffffu, s, 4);
            if (q == 0)
                out[(size_t)(gb0 + row) * TTOT + (TTOT - 1)] = s + bo;
        }
    }
}

// ---------------------------------------------------------------------------
extern "C" void kernel_launch(void* const* d_in, const int* in_sizes, int n_in,
                              void* d_out, int out_size) {
    const float* x    = (const float*)d_in[0];
    const float* Wih1 = (const float*)d_in[1];
    const float* Whh1 = (const float*)d_in[2];
    const float* bih1 = (const float*)d_in[3];
    const float* bhh1 = (const float*)d_in[4];
    const float* Wih2 = (const float*)d_in[5];
    const float* Whh2 = (const float*)d_in[6];
    const float* bih2 = (const float*)d_in[7];
    const float* bhh2 = (const float*)d_in[8];
    const float* Wout = (const float*)d_in[9];
    const float* bouT = (const float*)d_in[10];
    float* out = (float*)d_out;

    prep_weights<<<64, 256>>>(Wih1, Whh1, bih1, bhh1, Wih2, Whh2, bih2, bhh2);
    lstm_main<<<NCTA, TPB>>>(x, Wout, bouT, out);
}